// round 4
// baseline (speedup 1.0000x reference)
#include <cuda_runtime.h>

typedef unsigned int u32;
typedef unsigned long long u64;
typedef unsigned char u8;
typedef unsigned short u16;

#define NSEG 2621440u      // voxels per sample == template size
#define NSAMP 8
#define SEGS 9             // 8 samples + 1 template
#define TPB 256
#define IPT 16
#define TILE 4096          // TPB*IPT
#define TILES 640          // NSEG / TILE (exact)

// Static device scratch
__device__ u64 g_bufA[(size_t)SEGS * NSEG];
__device__ u64 g_bufB[(size_t)SEGS * NSEG];
__device__ u32 g_th[4ull * SEGS * 256 * TILES];  // per (pass,seg,digit,tile) counts -> offsets
__device__ u32 g_ghist[4 * SEGS * 256];          // global digit hist per (pass,seg)
__device__ u32 g_gbase[4 * SEGS * 256];          // exclusive scan of g_ghist
__device__ float g_tval[NSEG];                   // sorted template values

__device__ __forceinline__ u32 f2k(float f) {
    u32 u = __float_as_uint(f);
    return u ^ ((u & 0x80000000u) ? 0xFFFFFFFFu : 0x80000000u);
}
__device__ __forceinline__ float k2f(u32 u) {
    u ^= ((u & 0x80000000u) ? 0x80000000u : 0xFFFFFFFFu);
    return __uint_as_float(u);
}

// ---------------- zero pass-1..3 tile hists + global hists ----------------
__global__ void zero_k() {
    u32 i = blockIdx.x * blockDim.x + threadIdx.x;
    u32 stride = gridDim.x * blockDim.x;
    uint4 z = make_uint4(0, 0, 0, 0);
    // planes 1..3 of g_th (pass 0 plane is fully written by pack)
    u32 n4 = (3u * SEGS * 256 * TILES) / 4;
    uint4* p = reinterpret_cast<uint4*>(g_th + (size_t)SEGS * 256 * TILES);
    for (u32 j = i; j < n4; j += stride) p[j] = z;
    if (i < 4 * SEGS * 256) g_ghist[i] = 0;
}

// ---------------- fused pack + global 4-plane hist + pass-0 per-tile hist ----------------
__global__ void __launch_bounds__(TPB) pack_hist_k(const float* __restrict__ x,
                                                   const float* __restrict__ t) {
    __shared__ u32 h[4][256];
    const int tid = threadIdx.x;
    const int l = tid & 31;
    const int seg = blockIdx.y;
    const int tile = blockIdx.x;
    for (int i = tid; i < 4 * 256; i += TPB) (&h[0][0])[i] = 0;
    __syncthreads();

    const float* src = (seg < NSAMP) ? (x + (size_t)seg * NSEG) : t;
    u64* dst = g_bufA + (size_t)seg * NSEG;
    const u32 base = tile * TILE;
    #pragma unroll
    for (int k = 0; k < 4; k++) {
        u32 j = base + (u32)(k * TPB * 4) + tid * 4;
        float4 v = *reinterpret_cast<const float4*>(src + j);
        u32 kk[4] = { f2k(v.x), f2k(v.y), f2k(v.z), f2k(v.w) };
        #pragma unroll
        for (int e = 0; e < 4; e++) {
            dst[j + e] = ((u64)kk[e] << 32) | (j + e);
            atomicAdd(&h[0][kk[e] & 255u], 1u);
            atomicAdd(&h[1][(kk[e] >> 8) & 255u], 1u);
            u32 d2 = (kk[e] >> 16) & 255u;
            u32 m2 = __match_any_sync(0xFFFFFFFFu, d2);
            if ((int)(__ffs(m2) - 1) == l) atomicAdd(&h[2][d2], (u32)__popc(m2));
            u32 d3 = kk[e] >> 24;
            u32 m3 = __match_any_sync(0xFFFFFFFFu, d3);
            if ((int)(__ffs(m3) - 1) == l) atomicAdd(&h[3][d3], (u32)__popc(m3));
        }
    }
    __syncthreads();
    #pragma unroll
    for (int p = 0; p < 4; p++) {
        u32 c = h[p][tid];
        if (c) atomicAdd(&g_ghist[(p * SEGS + seg) * 256 + tid], c);
    }
    // pass-0 per-tile hist (digit-major layout for the tile scan)
    g_th[((size_t)(0 * SEGS + seg) * 256 + tid) * TILES + tile] = h[0][tid];
}

// ---------------- per-(pass,seg) exclusive digit scan ----------------
__global__ void gscan_k() {
    __shared__ u32 wsum[8];
    const int seg = blockIdx.x, p = blockIdx.y;
    const int t = threadIdx.x, l = t & 31, w = t >> 5;
    u32 tot = g_ghist[(p * SEGS + seg) * 256 + t];
    u32 v = tot;
    #pragma unroll
    for (int off = 1; off < 32; off <<= 1) {
        u32 n = __shfl_up_sync(0xFFFFFFFFu, v, off);
        if (l >= off) v += n;
    }
    if (l == 31) wsum[w] = v;
    __syncthreads();
    if (t == 0) {
        u32 run = 0;
        #pragma unroll
        for (int i = 0; i < 8; i++) { u32 c = wsum[i]; wsum[i] = run; run += c; }
    }
    __syncthreads();
    g_gbase[(p * SEGS + seg) * 256 + t] = wsum[w] + v - tot;
}

// ---------------- per-(seg,digit) scan over tiles: counts -> absolute offsets ----------------
// one warp per digit chain; blockIdx.x = seg, blockIdx.y = digit-group (8 digits/block)
__global__ void __launch_bounds__(256) tscan_k(int P) {
    const int seg = blockIdx.x;
    const int t = threadIdx.x, w = t >> 5, l = t & 31;
    const int d = blockIdx.y * 8 + w;
    u32* row = g_th + ((size_t)(P * SEGS + seg) * 256 + d) * TILES;
    u32 run = g_gbase[(P * SEGS + seg) * 256 + d];
    for (int c = 0; c < TILES; c += 32) {
        u32 v = row[c + l];
        u32 s = v;
        #pragma unroll
        for (int off = 1; off < 32; off <<= 1) {
            u32 n = __shfl_up_sync(0xFFFFFFFFu, s, off);
            if (l >= off) s += n;
        }
        row[c + l] = run + s - v;          // exclusive absolute offset
        run += __shfl_sync(0xFFFFFFFFu, s, 31);
    }
}

// ---------------- scatter: rank + smem exchange + coalesced write (+ next-pass tile hist) ----------------
// MODE 0: sorted u64 items -> other buffer
// MODE 1: fused epilogue  out[idx] = t_sorted[gp]   (samples, pass 3)
// MODE 2: g_tval[gp] = key-as-float                 (template, pass 3)
template<int PASS, int MODE, int HIST>
__global__ void __launch_bounds__(TPB, 3) scatter_k(float* __restrict__ outf, int segOff) {
    __shared__ __align__(16) u8 cnt8[IPT * 8 * 256];     // 32 KB, aliased as exchange later
    __shared__ u16 rb16[IPT * 256];                      // 8 KB
    __shared__ u32 delta[256];
    __shared__ u32 wsum[8];
    u64* ex = reinterpret_cast<u64*>(cnt8);              // 4096 u64 = 32 KB

    const int t = threadIdx.x;
    const int w = t >> 5;
    const int l = t & 31;
    const u32 lmlt = (1u << l) - 1u;
    const u32 tile = blockIdx.x;
    const int seg = blockIdx.y + segOff;
    constexpr int SHIFT = 32 + 8 * PASS;

    // zero counters
    u32* c32 = reinterpret_cast<u32*>(cnt8);
    #pragma unroll
    for (int i = 0; i < (IPT * 8 * 256 / 4) / TPB; i++) c32[i * TPB + t] = 0;
    __syncthreads();

    const u64* __restrict__ in = (PASS & 1) ? g_bufB : g_bufA;
    u64* __restrict__ outp     = (PASS & 1) ? g_bufA : g_bufB;
    const size_t sbase = (size_t)seg * NSEG;
    const size_t base = sbase + (size_t)tile * TILE;

    u64 item[IPT];
    #pragma unroll
    for (int k = 0; k < IPT; k++) item[k] = in[base + (size_t)k * TPB + t];

    // warp match ranking; leaders record per-(round,warp,digit) counts
    u32 lr0 = 0, lr1 = 0, lr2 = 0, lr3 = 0;
    #pragma unroll
    for (int k = 0; k < IPT; k++) {
        u32 d = (u32)(item[k] >> SHIFT) & 255u;
        u32 m = __match_any_sync(0xFFFFFFFFu, d);
        u32 r = __popc(m & lmlt);
        if (r == 0) cnt8[(k * 8 + w) * 256 + d] = (u8)__popc(m);
        if (k < 4)       lr0 |= r << (8 * k);
        else if (k < 8)  lr1 |= r << (8 * (k - 4));
        else if (k < 12) lr2 |= r << (8 * (k - 8));
        else             lr3 |= r << (8 * (k - 12));
    }
    __syncthreads();

    // digit t: tile total
    u32 tot = 0;
    #pragma unroll
    for (int c = 0; c < IPT * 8; c++) tot += cnt8[c * 256 + t];

    // block exclusive scan over 256 digit totals -> local_base
    u32 v = tot;
    #pragma unroll
    for (int off = 1; off < 32; off <<= 1) {
        u32 n = __shfl_up_sync(0xFFFFFFFFu, v, off);
        if (l >= off) v += n;
    }
    if (l == 31) wsum[w] = v;
    __syncthreads();
    if (t == 0) {
        u32 run = 0;
        #pragma unroll
        for (int i = 0; i < 8; i++) { u32 c = wsum[i]; wsum[i] = run; run += c; }
    }
    __syncthreads();
    const u32 local_base = wsum[w] + v - tot;

    // precomputed absolute offset for (seg, digit t, tile) — no lookback
    delta[t] = g_th[((size_t)(PASS * SEGS + seg) * 256 + t) * TILES + tile] - local_base;

    // per-(round,digit) local bases + per-cell warp prefixes
    u32 run2 = local_base;
    #pragma unroll
    for (int k = 0; k < IPT; k++) {
        rb16[k * 256 + t] = (u16)run2;
        u32 rs = run2;
        #pragma unroll
        for (int w2 = 0; w2 < 8; w2++) {
            u32 i = (u32)(k * 8 + w2) * 256 + t;
            u32 c = cnt8[i];
            cnt8[i] = (u8)(run2 - rs);
            run2 += c;
        }
    }
    __syncthreads();

    // tile-local sorted positions
    u16 lp[IPT];
    #pragma unroll
    for (int k = 0; k < IPT; k++) {
        u32 d = (u32)(item[k] >> SHIFT) & 255u;
        u32 r;
        if (k < 4)       r = (lr0 >> (8 * k)) & 255u;
        else if (k < 8)  r = (lr1 >> (8 * (k - 4))) & 255u;
        else if (k < 12) r = (lr2 >> (8 * (k - 8))) & 255u;
        else             r = (lr3 >> (8 * (k - 12))) & 255u;
        lp[k] = (u16)((u32)rb16[k * 256 + d] + (u32)cnt8[(k * 8 + w) * 256 + d] + r);
    }
    __syncthreads();   // done with cnt8/rb16 -> alias as exchange

    #pragma unroll
    for (int k = 0; k < IPT; k++) ex[lp[k]] = item[k];
    __syncthreads();

    // tile-sorted order -> coalesced digit-run writes; build next-pass tile hist
    #pragma unroll
    for (int k = 0; k < IPT; k++) {
        u32 p2 = (u32)k * TPB + t;
        u64 it = ex[p2];
        u32 d = (u32)(it >> SHIFT) & 255u;
        u32 gp = delta[d] + p2;
        if (HIST) {
            u32 d2 = (u32)(it >> (SHIFT + 8)) & 255u;
            atomicAdd(&g_th[((size_t)((PASS + 1) * SEGS + seg) * 256 + d2) * TILES + (gp >> 12)], 1u);
        }
        if (MODE == 0) {
            outp[sbase + gp] = it;
        } else if (MODE == 2) {
            g_tval[gp] = k2f((u32)(it >> 32));
        } else {
            outf[sbase + (u32)it] = __ldg(&g_tval[gp]);
        }
    }
}

extern "C" void kernel_launch(void* const* d_in, const int* in_sizes, int n_in,
                              void* d_out, int out_size) {
    const float* x  = (const float*)d_in[0];
    const float* bv = (const float*)d_in[1];
    float* out = (float*)d_out;

    zero_k<<<2048, TPB>>>();
    pack_hist_k<<<dim3(TILES, SEGS), TPB>>>(x, bv);
    gscan_k<<<dim3(SEGS, 4), 256>>>();

    tscan_k<<<dim3(SEGS, 32), 256>>>(0);
    scatter_k<0, 0, 1><<<dim3(TILES, SEGS), TPB>>>(nullptr, 0);   // A -> B, builds g_th[1]

    tscan_k<<<dim3(SEGS, 32), 256>>>(1);
    scatter_k<1, 0, 1><<<dim3(TILES, SEGS), TPB>>>(nullptr, 0);   // B -> A, builds g_th[2]

    tscan_k<<<dim3(SEGS, 32), 256>>>(2);
    scatter_k<2, 0, 1><<<dim3(TILES, SEGS), TPB>>>(nullptr, 0);   // A -> B, builds g_th[3]

    tscan_k<<<dim3(SEGS, 32), 256>>>(3);
    scatter_k<3, 2, 0><<<dim3(TILES, 1), TPB>>>(nullptr, NSAMP);  // template -> g_tval
    scatter_k<3, 1, 0><<<dim3(TILES, NSAMP), TPB>>>(out, 0);      // fused epilogue
}

// round 5
// speedup vs baseline: 1.6184x; 1.6184x over previous
#include <cuda_runtime.h>

typedef unsigned int u32;
typedef unsigned long long u64;
typedef unsigned char u8;

#define NSEG 2621440u      // voxels per sample == template size
#define NSAMP 8
#define SEGS 9             // 8 samples + 1 template
#define TPB 256
#define IPT 16
#define TILE 4096          // TPB*IPT
#define TILES 640          // NSEG / TILE (exact)

// Static device scratch
__device__ u64 g_bufA[(size_t)SEGS * NSEG];
__device__ u64 g_bufB[(size_t)SEGS * NSEG];
__device__ u32 g_th[4ull * SEGS * 256 * TILES];  // per (pass,seg,digit,tile) counts -> abs offsets
__device__ u32 g_ghist[4 * SEGS * 256];          // global digit hist per (pass,seg)
__device__ u32 g_gbase[4 * SEGS * 256];          // exclusive scan of g_ghist
__device__ float g_tval[NSEG];                   // sorted template values

__device__ __forceinline__ u32 f2k(float f) {
    u32 u = __float_as_uint(f);
    return u ^ ((u & 0x80000000u) ? 0xFFFFFFFFu : 0x80000000u);
}
__device__ __forceinline__ float k2f(u32 u) {
    u ^= ((u & 0x80000000u) ? 0x80000000u : 0xFFFFFFFFu);
    return __uint_as_float(u);
}

// ---------------- zero global hists (rest is fully overwritten each run) ----------------
__global__ void zero_k() {
    u32 i = blockIdx.x * blockDim.x + threadIdx.x;
    if (i < 4 * SEGS * 256) g_ghist[i] = 0;
}

// ---------------- fused pack + global 4-plane hist + pass-0 per-tile hist ----------------
__global__ void __launch_bounds__(TPB) pack_hist_k(const float* __restrict__ x,
                                                   const float* __restrict__ t) {
    __shared__ u32 h[4][256];
    const int tid = threadIdx.x;
    const int l = tid & 31;
    const int seg = blockIdx.y;
    const int tile = blockIdx.x;
    for (int i = tid; i < 4 * 256; i += TPB) (&h[0][0])[i] = 0;
    __syncthreads();

    const float* src = (seg < NSAMP) ? (x + (size_t)seg * NSEG) : t;
    u64* dst = g_bufA + (size_t)seg * NSEG;
    const u32 base = tile * TILE;
    #pragma unroll
    for (int k = 0; k < 4; k++) {
        u32 j = base + (u32)(k * TPB * 4) + tid * 4;
        float4 v = *reinterpret_cast<const float4*>(src + j);
        u32 kk[4] = { f2k(v.x), f2k(v.y), f2k(v.z), f2k(v.w) };
        #pragma unroll
        for (int e = 0; e < 4; e++) {
            dst[j + e] = ((u64)kk[e] << 32) | (j + e);
            atomicAdd(&h[0][kk[e] & 255u], 1u);
            atomicAdd(&h[1][(kk[e] >> 8) & 255u], 1u);
            u32 d2 = (kk[e] >> 16) & 255u;
            u32 m2 = __match_any_sync(0xFFFFFFFFu, d2);
            if ((int)(__ffs(m2) - 1) == l) atomicAdd(&h[2][d2], (u32)__popc(m2));
            u32 d3 = kk[e] >> 24;
            u32 m3 = __match_any_sync(0xFFFFFFFFu, d3);
            if ((int)(__ffs(m3) - 1) == l) atomicAdd(&h[3][d3], (u32)__popc(m3));
        }
    }
    __syncthreads();
    #pragma unroll
    for (int p = 0; p < 4; p++) {
        u32 c = h[p][tid];
        if (c) atomicAdd(&g_ghist[(p * SEGS + seg) * 256 + tid], c);
    }
    // pass-0 per-tile hist (digit-major for the tile scan)
    g_th[((size_t)(0 * SEGS + seg) * 256 + tid) * TILES + tile] = h[0][tid];
}

// ---------------- per-tile hist for passes 1..3 (reads key u32 only) ----------------
template<int PASS>
__global__ void __launch_bounds__(TPB) hist_k() {
    __shared__ u32 h[8][256];
    const u32* __restrict__ in = reinterpret_cast<const u32*>((PASS & 1) ? g_bufB : g_bufA);
    const int t = threadIdx.x;
    const int w = t >> 5;
    const int tile = blockIdx.x, seg = blockIdx.y;
    #pragma unroll
    for (int i = t; i < 8 * 256; i += TPB) (&h[0][0])[i] = 0;
    __syncthreads();
    const size_t base = 2 * ((size_t)seg * NSEG + (size_t)tile * TILE) + 1;
    #pragma unroll
    for (int k = 0; k < IPT; k++) {
        u32 key = __ldcs(&in[base + 2 * (size_t)(k * TPB + t)]);
        atomicAdd(&h[w][(key >> (8 * PASS)) & 255u], 1u);
    }
    __syncthreads();
    u32 s = 0;
    #pragma unroll
    for (int w2 = 0; w2 < 8; w2++) s += h[w2][t];
    g_th[((size_t)(PASS * SEGS + seg) * 256 + t) * TILES + tile] = s;
}

// ---------------- per-(pass,seg) exclusive digit scan ----------------
__global__ void gscan_k() {
    __shared__ u32 wsum[8];
    const int seg = blockIdx.x, p = blockIdx.y;
    const int t = threadIdx.x, l = t & 31, w = t >> 5;
    u32 tot = g_ghist[(p * SEGS + seg) * 256 + t];
    u32 v = tot;
    #pragma unroll
    for (int off = 1; off < 32; off <<= 1) {
        u32 n = __shfl_up_sync(0xFFFFFFFFu, v, off);
        if (l >= off) v += n;
    }
    if (l == 31) wsum[w] = v;
    __syncthreads();
    if (t == 0) {
        u32 run = 0;
        #pragma unroll
        for (int i = 0; i < 8; i++) { u32 c = wsum[i]; wsum[i] = run; run += c; }
    }
    __syncthreads();
    g_gbase[(p * SEGS + seg) * 256 + t] = wsum[w] + v - tot;
}

// ---------------- per-(seg,digit) scan over tiles: counts -> absolute offsets ----------------
__global__ void __launch_bounds__(256) tscan_k(int P) {
    const int seg = blockIdx.x;
    const int t = threadIdx.x, w = t >> 5, l = t & 31;
    const int d = blockIdx.y * 8 + w;
    u32* row = g_th + ((size_t)(P * SEGS + seg) * 256 + d) * TILES;
    u32 run = g_gbase[(P * SEGS + seg) * 256 + d];
    for (int c = 0; c < TILES; c += 32) {
        u32 v = row[c + l];
        u32 s = v;
        #pragma unroll
        for (int off = 1; off < 32; off <<= 1) {
            u32 n = __shfl_up_sync(0xFFFFFFFFu, s, off);
            if (l >= off) s += n;
        }
        row[c + l] = run + s - v;          // exclusive absolute offset
        run += __shfl_sync(0xFFFFFFFFu, s, 31);
    }
}

// ---------------- stable rank + direct scatter (R1's proven kernel) ----------------
// MODE 0: sorted u64 items -> other buffer
// MODE 1: fused epilogue  out[idx] = t_sorted[gp]   (samples, pass 3)
// MODE 2: g_tval[gp] = key-as-float                 (template, pass 3)
template<int PASS, int MODE>
__global__ void __launch_bounds__(TPB) scatter_k(float* __restrict__ outf, int segOff) {
    __shared__ u8 cnt8[IPT * 8 * 256];   // 32 KB: per (round,warp,digit) counts -> warp prefixes
    __shared__ u32 rb[IPT * 256];        // 16 KB: absolute base per (round, digit)

    const int t = threadIdx.x;
    const int w = t >> 5;
    const int l = t & 31;
    const u32 lmlt = (1u << l) - 1u;
    const u32 tile = blockIdx.x;
    const int seg = blockIdx.y + segOff;
    constexpr int SHIFT = 32 + 8 * PASS;

    const u64* __restrict__ in = (PASS & 1) ? g_bufB : g_bufA;
    u64* __restrict__ outp     = (PASS & 1) ? g_bufA : g_bufB;
    const size_t sbase = (size_t)seg * NSEG;
    const size_t base = sbase + (size_t)tile * TILE;

    // issue global loads early (striped; streaming hint)
    u64 item[IPT];
    #pragma unroll
    for (int k = 0; k < IPT; k++) item[k] = __ldcs(&in[base + (size_t)k * TPB + t]);

    // absolute digit base for this (seg, digit t, tile) — precomputed, no lookback
    u32 run = g_th[((size_t)(PASS * SEGS + seg) * 256 + t) * TILES + tile];

    // zero counters
    u32* c32 = reinterpret_cast<u32*>(cnt8);
    #pragma unroll
    for (int i = 0; i < (IPT * 8 * 256 / 4) / TPB; i++) c32[i * TPB + t] = 0;
    __syncthreads();

    // warp match ranking; leaders record per-(round,warp,digit) counts
    u32 lr0 = 0, lr1 = 0, lr2 = 0, lr3 = 0;
    #pragma unroll
    for (int k = 0; k < IPT; k++) {
        u32 d = (u32)(item[k] >> SHIFT) & 255u;
        u32 m = __match_any_sync(0xFFFFFFFFu, d);
        u32 r = __popc(m & lmlt);
        if (r == 0) cnt8[(k * 8 + w) * 256 + d] = (u8)__popc(m);
        if (k < 4)       lr0 |= r << (8 * k);
        else if (k < 8)  lr1 |= r << (8 * (k - 4));
        else if (k < 12) lr2 |= r << (8 * (k - 8));
        else             lr3 |= r << (8 * (k - 12));
    }
    __syncthreads();

    // thread t owns digit t; serial prefix over 128 (round, warp) cells
    #pragma unroll
    for (int k = 0; k < IPT; k++) {
        rb[k * 256 + t] = run;
        u32 rs = run;
        #pragma unroll
        for (int w2 = 0; w2 < 8; w2++) {
            u32 i = (u32)(k * 8 + w2) * 256 + t;
            u32 c = cnt8[i];
            cnt8[i] = (u8)(run - rs);   // warp prefix relative to round start (<= 224)
            run += c;
        }
    }
    __syncthreads();

    // final positions, direct global write
    #pragma unroll
    for (int k = 0; k < IPT; k++) {
        u32 d = (u32)(item[k] >> SHIFT) & 255u;
        u32 r;
        if (k < 4)       r = (lr0 >> (8 * k)) & 255u;
        else if (k < 8)  r = (lr1 >> (8 * (k - 4))) & 255u;
        else if (k < 12) r = (lr2 >> (8 * (k - 8))) & 255u;
        else             r = (lr3 >> (8 * (k - 12))) & 255u;
        u32 pos = rb[k * 256 + d] + (u32)cnt8[(k * 8 + w) * 256 + d] + r;
        if (MODE == 0) {
            outp[sbase + pos] = item[k];
        } else if (MODE == 2) {
            g_tval[pos] = k2f((u32)(item[k] >> 32));
        } else {
            outf[sbase + (u32)item[k]] = __ldg(&g_tval[pos]);
        }
    }
}

extern "C" void kernel_launch(void* const* d_in, const int* in_sizes, int n_in,
                              void* d_out, int out_size) {
    const float* x  = (const float*)d_in[0];
    const float* bv = (const float*)d_in[1];
    float* out = (float*)d_out;

    zero_k<<<36, 256>>>();
    pack_hist_k<<<dim3(TILES, SEGS), TPB>>>(x, bv);
    gscan_k<<<dim3(SEGS, 4), 256>>>();

    tscan_k<<<dim3(SEGS, 32), 256>>>(0);
    scatter_k<0, 0><<<dim3(TILES, SEGS), TPB>>>(nullptr, 0);   // A -> B

    hist_k<1><<<dim3(TILES, SEGS), TPB>>>();
    gscanfix:;
    tscan_k<<<dim3(SEGS, 32), 256>>>(1);
    scatter_k<1, 0><<<dim3(TILES, SEGS), TPB>>>(nullptr, 0);   // B -> A

    hist_k<2><<<dim3(TILES, SEGS), TPB>>>();
    tscan_k<<<dim3(SEGS, 32), 256>>>(2);
    scatter_k<2, 0><<<dim3(TILES, SEGS), TPB>>>(nullptr, 0);   // A -> B

    hist_k<3><<<dim3(TILES, SEGS), TPB>>>();
    tscan_k<<<dim3(SEGS, 32), 256>>>(3);
    scatter_k<3, 2><<<dim3(TILES, 1), TPB>>>(nullptr, NSAMP);  // template -> g_tval
    scatter_k<3, 1><<<dim3(TILES, NSAMP), TPB>>>(out, 0);      // fused epilogue
}